// round 17
// baseline (speedup 1.0000x reference)
#include <cuda_runtime.h>
#include <cstdint>
#include <cstddef>

// Xonv2D: out[b,o,h,w] = sum_{c,kh,kw} x[b,c,h+kh-1,w+kw-1] * W[h,w,o,c,kh,kw] + bias[h,w,o]
// B=4, CIN=COUT=16, K=3, H=W=128. Weights = 151MB streamed once -> HBM-bound.
// Round 17: x pre-transposed to halo-padded xT[h'][w'][c][b] fp32 (L2-resident).
// Main loop reads x via LDG.128 (1 line/warp-instr, no smem x tile, no CVTs,
// no bounds checks). FFMA2 batch-pair accumulators (R15). ONE barrier/iter
// (double-buffered sout). Ring-2 weight TMA, 3 CTAs/SM x 256 thr.

static constexpr int Hc = 128, Wc = 128;
static constexpr int GROUPS = 4096;                      // 4-pixel groups
static constexpr int FLOATS_PER_PX = 16 * 16 * 9;        // 2304
static constexpr int CHUNK_FLOATS  = 4 * FLOATS_PER_PX;  // 9216
static constexpr int CHUNK_BYTES   = CHUNK_FLOATS * 4;   // 36864
static constexpr int SMEM_OUT_OFF  = 2 * CHUNK_BYTES;            // 73728
static constexpr int SMEM_MBAR_OFF = SMEM_OUT_OFF + 2 * 1024;    // 75776 (double sout)
static constexpr int SMEM_TOTAL    = SMEM_MBAR_OFF + 16;         // 75792 (x3 <= 233472)
static constexpr int GRID          = 456;                // 3 CTAs/SM * 152 SMs
static constexpr int NT            = 256;

// Halo-padded transposed x: [h'][w'][c][b], h',w' in 0..129, zeros at borders.
static constexpr int XT_P = 130;
__device__ float g_xT[XT_P * XT_P * 64];

// Transpose: 260 blocks = (h' 0..129) x (w-half). Coalesced read + coalesced write
// via an smem stage (65-word pitch -> conflict-free).
__global__ __launch_bounds__(256) void transpose_kernel(const float* __restrict__ x) {
    __shared__ float s[65 * 65];
    const int hp   = blockIdx.x >> 1;        // 0..129
    const int half = blockIdx.x & 1;
    const int wp0  = half * 65;              // w' range [wp0, wp0+64]
    const int wbase = wp0 - 1;
    const int h = hp - 1;
    const bool hvalid = ((unsigned)h < 128u);

    if (hvalid) {
        for (int i = threadIdx.x; i < 64 * 65; i += 256) {
            const int wl = i % 65;
            const int cb = i / 65;           // b*16+c
            const int c  = cb & 15;
            const int b  = cb >> 4;
            const int w  = wbase + wl;
            const float v = ((unsigned)w < 128u)
                            ? __ldg(x + ((size_t)cb * 128 + h) * 128 + w) : 0.0f;
            s[wl * 65 + c * 4 + b] = v;
        }
    }
    __syncthreads();
    for (int i = threadIdx.x; i < 65 * 64; i += 256) {
        const int cb2 = i & 63;              // c*4 + b
        const int wlp = i >> 6;              // 0..64
        const int wp  = wp0 + wlp;
        const int w   = wp - 1;
        float v = 0.0f;
        if (hvalid && (unsigned)w < 128u) v = s[wlp * 65 + cb2];
        g_xT[((size_t)hp * XT_P + wp) * 64 + cb2] = v;
    }
}

__device__ __forceinline__ uint32_t smem_u32(const void* p) {
    return (uint32_t)__cvta_generic_to_shared(p);
}
__device__ __forceinline__ void mbar_init(uint32_t a, uint32_t count) {
    asm volatile("mbarrier.init.shared.b64 [%0], %1;" :: "r"(a), "r"(count) : "memory");
}
__device__ __forceinline__ void mbar_expect_tx(uint32_t a, uint32_t bytes) {
    asm volatile("mbarrier.arrive.expect_tx.shared.b64 _, [%0], %1;" :: "r"(a), "r"(bytes) : "memory");
}
__device__ __forceinline__ void tma_bulk_g2s(uint32_t dst, const void* src, uint32_t bytes, uint32_t mbar) {
    asm volatile("cp.async.bulk.shared::cta.global.mbarrier::complete_tx::bytes [%0], [%1], %2, [%3];"
                 :: "r"(dst), "l"(src), "r"(bytes), "r"(mbar) : "memory");
}
__device__ __forceinline__ void mbar_wait(uint32_t a, uint32_t parity) {
    uint32_t done;
    asm volatile(
        "{\n\t.reg .pred p;\n\t"
        "mbarrier.try_wait.parity.acquire.cta.shared::cta.b64 p, [%1], %2;\n\t"
        "selp.b32 %0, 1, 0, p;\n\t}"
        : "=r"(done) : "r"(a), "r"(parity) : "memory");
    while (!done) {
        asm volatile(
            "{\n\t.reg .pred p;\n\t"
            "mbarrier.try_wait.parity.acquire.cta.shared::cta.b64 p, [%1], %2, 0x989680;\n\t"
            "selp.b32 %0, 1, 0, p;\n\t}"
            : "=r"(done) : "r"(a), "r"(parity) : "memory");
    }
}

// f32x2 helpers
__device__ __forceinline__ unsigned long long f32x2_pack(float lo, float hi) {
    unsigned long long r;
    asm("mov.b64 %0, {%1, %2};" : "=l"(r) : "f"(lo), "f"(hi));
    return r;
}
__device__ __forceinline__ unsigned long long f32x2_dup(float v) {
    unsigned long long r;
    asm("mov.b64 %0, {%1, %1};" : "=l"(r) : "f"(v));
    return r;
}
__device__ __forceinline__ void ffma2(unsigned long long& acc, unsigned long long a, unsigned long long b) {
    asm("fma.rn.f32x2 %0, %1, %2, %0;" : "+l"(acc) : "l"(a), "l"(b));
}
__device__ __forceinline__ float2 f32x2_unpack(unsigned long long v) {
    float2 r;
    asm("mov.b64 {%0, %1}, %2;" : "=f"(r.x), "=f"(r.y) : "l"(v));
    return r;
}

__global__ void __launch_bounds__(NT, 3)
xonv2d_kernel(const float* __restrict__ wts,
              const float* __restrict__ bias,
              float* __restrict__ out)
{
    extern __shared__ char smem[];
    float*   swt  = reinterpret_cast<float*>(smem);
    float*   sof  = reinterpret_cast<float*>(smem + SMEM_OUT_OFF);   // 2 x 256 floats
    float4*  sof4 = reinterpret_cast<float4*>(smem + SMEM_OUT_OFF);
    const uint32_t mb = smem_u32(smem + SMEM_MBAR_OFF);
    const uint32_t swt_u32 = smem_u32(smem);

    const int t   = threadIdx.x;
    const int bid = blockIdx.x;

    if (t == 0) { mbar_init(mb, 1); mbar_init(mb + 8, 1); }
    __syncthreads();

    // Prologue: weight TMA for chunks bid (slot0), bid+GRID (slot1).
    if (t == 0) {
        mbar_expect_tx(mb, CHUNK_BYTES);
        tma_bulk_g2s(swt_u32, wts + (size_t)bid * CHUNK_FLOATS, CHUNK_BYTES, mb);
        mbar_expect_tx(mb + 8, CHUNK_BYTES);
        tma_bulk_g2s(swt_u32 + CHUNK_BYTES,
                     wts + (size_t)(bid + GRID) * CHUNK_FLOATS, CHUNK_BYTES, mb + 8);
    }

    // Lane mapping: o0l=bit0, ch=bits1-3 (cin pair), o0h=bit4; warp: o0m=bit5, px=bits6-7.
    const int o0  = (t & 1) + 2 * ((t >> 4) & 1) + 4 * ((t >> 5) & 1);
    const int ch  = (t >> 1) & 7;
    const int px  = (t >> 6) & 3;
    const int wbase_f2 = px * (FLOATS_PER_PX / 2) + o0 * 72 + ch * 9;

    // bias prefetch for first chunk.
    float bs0 = 0.f, bs1 = 0.f, bs2 = 0.f, bs3 = 0.f;
    if (t < 64) {
        const float* bp = bias + (size_t)bid * 64 + (t & 15);
        bs0 = __ldg(bp); bs1 = __ldg(bp + 16); bs2 = __ldg(bp + 32); bs3 = __ldg(bp + 48);
    }

    for (int j = 0, gi = bid; gi < GROUPS; j++, gi += GRID) {
        const int slot   = j & 1;
        const int parity = (j >> 1) & 1;

        // bias prefetch for next chunk (LDGs overlap the weight wait).
        float bn0 = 0.f, bn1 = 0.f, bn2 = 0.f, bn3 = 0.f;
        if (t < 64 && gi + GRID < GROUPS) {
            const float* bp = bias + (size_t)(gi + GRID) * 64 + (t & 15);
            bn0 = __ldg(bp); bn1 = __ldg(bp + 16); bn2 = __ldg(bp + 32); bn3 = __ldg(bp + 48);
        }

        mbar_wait(mb + slot * 8, parity);  // weights for chunk gi ready

        // x base: pixel (h,w); tap (r,s,cc) offsets are compile-time immediates.
        const int pix = gi * 4 + px;
        const int h   = pix >> 7;
        const int w   = pix & 127;
        const float* xg = g_xT + ((size_t)(h * XT_P + w)) * 64 + ch * 8;

        const float2* wp = reinterpret_cast<const float2*>(swt + slot * CHUNK_FLOATS) + wbase_f2;

        // Packed accumulators: (b0,b1),(b2,b3) pairs for couts o0 and o0+8.
        unsigned long long c0lo = 0ull, c0hi = 0ull, c1lo = 0ull, c1hi = 0ull;

        #pragma unroll
        for (int k = 0; k < 9; k++) {
            const float2 w0v = wp[k];          // cout o0
            const float2 w1v = wp[k + 576];    // cout o0+8
            #pragma unroll
            for (int e = 0; e < 2; e++) {
                const int f   = 2 * k + e;     // 0..17
                const int cc  = f / 9;
                const int tap = f % 9;
                const int r   = tap / 3;
                const int s   = tap % 3;
                const float4 xv = __ldg(reinterpret_cast<const float4*>(
                                          xg + (r * XT_P + s) * 64 + cc * 4));
                const unsigned long long xlo = f32x2_pack(xv.x, xv.y);  // reg-aligned
                const unsigned long long xhi = f32x2_pack(xv.z, xv.w);
                const unsigned long long wa2 = f32x2_dup(e ? w0v.y : w0v.x);
                const unsigned long long wb2 = f32x2_dup(e ? w1v.y : w1v.x);
                ffma2(c0lo, wa2, xlo);
                ffma2(c0hi, wa2, xhi);
                ffma2(c1lo, wb2, xlo);
                ffma2(c1hi, wb2, xhi);
            }
        }

        const float2 u0 = f32x2_unpack(c0lo);
        const float2 u1 = f32x2_unpack(c0hi);
        const float2 u2 = f32x2_unpack(c1lo);
        const float2 u3 = f32x2_unpack(c1hi);
        float a00 = u0.x, a01 = u0.y, a02 = u1.x, a03 = u1.y;
        float a10 = u2.x, a11 = u2.y, a12 = u3.x, a13 = u3.y;

        // Reduce over ch (lane bits 1-3): 3 butterflies.
        #pragma unroll
        for (int m = 2; m <= 8; m <<= 1) {
            a00 += __shfl_xor_sync(0xffffffffu, a00, m);
            a01 += __shfl_xor_sync(0xffffffffu, a01, m);
            a02 += __shfl_xor_sync(0xffffffffu, a02, m);
            a03 += __shfl_xor_sync(0xffffffffu, a03, m);
            a10 += __shfl_xor_sync(0xffffffffu, a10, m);
            a11 += __shfl_xor_sync(0xffffffffu, a11, m);
            a12 += __shfl_xor_sync(0xffffffffu, a12, m);
            a13 += __shfl_xor_sync(0xffffffffu, a13, m);
        }

        // Stage outputs into the double-buffered sout (buffer = slot).
        if (ch == 0) {
            float* so = sof + slot * 256;
            const int o1 = o0 + 8;
            so[(0 * 16 + o0) * 4 + px] = a00;
            so[(1 * 16 + o0) * 4 + px] = a01;
            so[(2 * 16 + o0) * 4 + px] = a02;
            so[(3 * 16 + o0) * 4 + px] = a03;
            so[(0 * 16 + o1) * 4 + px] = a10;
            so[(1 * 16 + o1) * 4 + px] = a11;
            so[(2 * 16 + o1) * 4 + px] = a12;
            so[(3 * 16 + o1) * 4 + px] = a13;
        }
        __syncthreads();   // S: sout(slot) ready; all weight-slot reads of chunk j done

        // Weight TMA for chunk j+2 into this (now free) slot.
        if (t == 0) {
            const int gn = gi + 2 * GRID;
            if (gn < GROUPS) {
                mbar_expect_tx(mb + slot * 8, CHUNK_BYTES);
                tma_bulk_g2s(swt_u32 + (uint32_t)slot * CHUNK_BYTES,
                             wts + (size_t)gn * CHUNK_FLOATS, CHUNK_BYTES, mb + slot * 8);
            }
        }

        // Coalesced write: thread t<64 -> (b = t>>4, o = t&15), float4 over 4 pixels.
        if (t < 64) {
            float4 v = sof4[slot * 64 + t];
            v.x += bs0; v.y += bs1; v.z += bs2; v.w += bs3;
            *reinterpret_cast<float4*>(out + (size_t)t * (Hc * Wc) + gi * 4) = v;
            bs0 = bn0; bs1 = bn1; bs2 = bn2; bs3 = bn3;
        }
    }
}

extern "C" void kernel_launch(void* const* d_in, const int* in_sizes, int n_in,
                              void* d_out, int out_size) {
    const float* x    = (const float*)d_in[0];
    const float* wts  = (const float*)d_in[1];
    const float* bias = (const float*)d_in[2];
    float* out        = (float*)d_out;

    cudaFuncSetAttribute(xonv2d_kernel, cudaFuncAttributeMaxDynamicSharedMemorySize, SMEM_TOTAL);

    transpose_kernel<<<2 * XT_P, 256>>>(x);
    xonv2d_kernel<<<GRID, NT, SMEM_TOTAL>>>(wts, bias, out);
}